// round 1
// baseline (speedup 1.0000x reference)
#include <cuda_runtime.h>
#include <math.h>

#define NN 5000
#define EE 40000
#define EP 45000      // EE + NN self loops
#define HH 8
#define AFS 520       // padded row stride for node-feature buffers (max width 516)

// ---------------- scratch (static device globals; no allocation) ----------------
__device__ float g_af[2][NN * AFS];      // ping-pong layer inputs [c.., coords.., feat..]
__device__ float g_h[NN * 4096];         // GEMM output h = af @ W (max H*C = 4096)
__device__ float g_es[NN * HH];          // per-node src attention scores
__device__ float g_ed[NN * HH];          // per-node dst attention scores
__device__ float g_alpha[EP * HH];       // softmaxed attention per (sorted-edge, head)
__device__ int   g_cnt[NN];
__device__ int   g_pos[NN];
__device__ int   g_rowptr[NN + 1];
__device__ int   g_srcS[EP];             // src node of edges sorted by dst (CSR order)

__device__ __forceinline__ float seluf(float x) {
    const float sc = 1.0507009873554805f, al = 1.6732632423543772f;
    return x > 0.f ? sc * x : sc * al * (expf(x) - 1.f);
}
__device__ __forceinline__ int edge_src(const int* e, int i) {
    return i < EE ? e[i] : i - EE;
}
__device__ __forceinline__ int edge_dst(const int* e, int i) {
    return i < EE ? e[EE + i] : i - EE;
}

// ---------------- CSR build ----------------
__global__ void k_init() {
    int i = blockIdx.x * blockDim.x + threadIdx.x;
    if (i < NN) { g_cnt[i] = 0; g_pos[i] = 0; }
}
__global__ void k_count(const int* __restrict__ eidx) {
    int i = blockIdx.x * blockDim.x + threadIdx.x;
    if (i < EP) atomicAdd(&g_cnt[edge_dst(eidx, i)], 1);
}
__global__ void k_scan() {   // single block, 1024 threads, 5 elems/thread
    __shared__ int sh[1024];
    const int CH = 5;
    int t = threadIdx.x;
    int base = t * CH;
    int loc[CH]; int s = 0;
    #pragma unroll
    for (int i = 0; i < CH; i++) {
        int idx = base + i;
        int v = (idx < NN) ? g_cnt[idx] : 0;
        loc[i] = s; s += v;
    }
    sh[t] = s;
    __syncthreads();
    for (int off = 1; off < 1024; off <<= 1) {
        int v = (t >= off) ? sh[t - off] : 0;
        __syncthreads();
        sh[t] += v;
        __syncthreads();
    }
    int excl = sh[t] - s;
    #pragma unroll
    for (int i = 0; i < CH; i++) {
        int idx = base + i;
        if (idx < NN) g_rowptr[idx] = excl + loc[i];
    }
    if (t == 1023) g_rowptr[NN] = sh[1023];
}
__global__ void k_scatter(const int* __restrict__ eidx) {
    int i = blockIdx.x * blockDim.x + threadIdx.x;
    if (i >= EP) return;
    int d = edge_dst(eidx, i);
    int p = atomicAdd(&g_pos[d], 1);
    g_srcS[g_rowptr[d] + p] = edge_src(eidx, i);
}

// ---------------- layer 0: feat0 = selu(data @ W0 + b0); af1 = [coord, feat0] ----------------
__global__ void k_layer0(const float* __restrict__ data, const float* __restrict__ W0,
                         const float* __restrict__ b0) {
    int n = blockIdx.x;
    int c = threadIdx.x;           // 256 threads = 256 output cols
    __shared__ float d[16];
    if (c < 10) d[c] = data[n * 10 + c];
    __syncthreads();
    float s = b0[c];
    #pragma unroll
    for (int k = 0; k < 10; k++) s = fmaf(d[k], W0[k * 256 + c], s);
    g_af[0][n * AFS + 2 + c] = seluf(s);
    if (c < 2) g_af[0][n * AFS + c] = d[c];
}

// ---------------- fp32 GEMM: g_h[M,Ncols] = g_af[sel][M,K] @ B[K,Ncols] ----------------
// 128x128 block, BK=8, 256 threads, 8x8 per thread.
__global__ void __launch_bounds__(256) k_gemm(int sel, const float* __restrict__ B,
                                              int M, int Ncols, int K) {
    __shared__ float Asm[8][128];
    __shared__ float Bsm[8][128];
    const float* A = g_af[sel];
    float* C = g_h;
    const int bm = blockIdx.y * 128, bn = blockIdx.x * 128;
    const int tid = threadIdx.x;
    const int tr = tid >> 4, tc = tid & 15;
    float acc[8][8];
    #pragma unroll
    for (int i = 0; i < 8; i++)
        #pragma unroll
        for (int j = 0; j < 8; j++) acc[i][j] = 0.f;

    for (int k0 = 0; k0 < K; k0 += 8) {
        #pragma unroll
        for (int i = 0; i < 4; i++) {
            int idx = i * 256 + tid;
            int m = idx >> 3, k = idx & 7;
            int gm = bm + m, gk = k0 + k;
            Asm[k][m] = (gm < M && gk < K) ? A[gm * AFS + gk] : 0.f;
        }
        #pragma unroll
        for (int i = 0; i < 4; i++) {
            int idx = i * 256 + tid;
            int k = idx >> 7, n = idx & 127;
            int gk = k0 + k, gn = bn + n;
            Bsm[k][n] = (gk < K && gn < Ncols) ? B[gk * Ncols + gn] : 0.f;
        }
        __syncthreads();
        #pragma unroll
        for (int k = 0; k < 8; k++) {
            float4 a0 = *(const float4*)&Asm[k][tr * 8];
            float4 a1 = *(const float4*)&Asm[k][tr * 8 + 4];
            float4 b0 = *(const float4*)&Bsm[k][tc * 4];
            float4 b1 = *(const float4*)&Bsm[k][64 + tc * 4];
            float am[8] = {a0.x, a0.y, a0.z, a0.w, a1.x, a1.y, a1.z, a1.w};
            float bv[8] = {b0.x, b0.y, b0.z, b0.w, b1.x, b1.y, b1.z, b1.w};
            #pragma unroll
            for (int i = 0; i < 8; i++)
                #pragma unroll
                for (int j = 0; j < 8; j++) acc[i][j] = fmaf(am[i], bv[j], acc[i][j]);
        }
        __syncthreads();
    }
    #pragma unroll
    for (int i = 0; i < 8; i++) {
        int gm = bm + tr * 8 + i;
        if (gm >= M) continue;
        #pragma unroll
        for (int j = 0; j < 8; j++) {
            int gn = bn + ((j < 4) ? tc * 4 + j : 64 + tc * 4 + (j - 4));
            if (gn < Ncols) C[gm * Ncols + gn] = acc[i][j];
        }
    }
}

// ---------------- per-node attention scores: es/ed[n,h] = <h[n,h,:], a_{s,d}[h,:]> ----------------
__global__ void k_scores(const float* __restrict__ asrc, const float* __restrict__ adst, int C) {
    int n = blockIdx.x;
    int wid = threadIdx.x >> 5, lane = threadIdx.x & 31;   // warp = head
    const float* hr = g_h + n * (HH * C) + wid * C;
    const float* as = asrc + wid * C;
    const float* ad = adst + wid * C;
    float s1 = 0.f, s2 = 0.f;
    for (int c = lane; c < C; c += 32) {
        float v = hr[c];
        s1 = fmaf(v, as[c], s1);
        s2 = fmaf(v, ad[c], s2);
    }
    #pragma unroll
    for (int off = 16; off > 0; off >>= 1) {
        s1 += __shfl_xor_sync(0xFFFFFFFFu, s1, off);
        s2 += __shfl_xor_sync(0xFFFFFFFFu, s2, off);
    }
    if (!lane) { g_es[n * HH + wid] = s1; g_ed[n * HH + wid] = s2; }
}

// ---------------- edge softmax over dst segments (warp per dst node) ----------------
__global__ void k_softmax() {
    int warp = (blockIdx.x * blockDim.x + threadIdx.x) >> 5;
    if (warp >= NN) return;
    int lane = threadIdx.x & 31;
    int n = warp;
    int beg = g_rowptr[n], end = g_rowptr[n + 1];
    int el = lane >> 3;        // 4 edge slots
    int hh = lane & 7;         // 8 heads
    float edv = g_ed[n * HH + hh];

    float mx = -INFINITY;
    for (int s = beg; s < end; s += 4) {
        int si = s + el;
        float lg = -INFINITY;
        if (si < end) {
            float x = g_es[g_srcS[si] * HH + hh] + edv;
            lg = x >= 0.f ? x : 0.2f * x;
        }
        mx = fmaxf(mx, lg);
    }
    mx = fmaxf(mx, __shfl_xor_sync(0xFFFFFFFFu, mx, 8));
    mx = fmaxf(mx, __shfl_xor_sync(0xFFFFFFFFu, mx, 16));

    float se = 0.f;
    for (int s = beg; s < end; s += 4) {
        int si = s + el;
        if (si < end) {
            float x = g_es[g_srcS[si] * HH + hh] + edv;
            x = x >= 0.f ? x : 0.2f * x;
            se += expf(x - mx);
        }
    }
    se += __shfl_xor_sync(0xFFFFFFFFu, se, 8);
    se += __shfl_xor_sync(0xFFFFFFFFu, se, 16);
    float inv = 1.f / se;

    for (int s = beg; s < end; s += 4) {
        int si = s + el;
        if (si < end) {
            float x = g_es[g_srcS[si] * HH + hh] + edv;
            x = x >= 0.f ? x : 0.2f * x;
            g_alpha[si * HH + hh] = expf(x - mx) * inv;
        }
    }
}

// ---------------- aggregation + coord update + next-layer assembly (layers 1..3) ----------------
// af_next = [c_k (2) | af_k[:,0:copyw] | selu(mean_h agg + bias)]
__global__ void k_aggregate(int sel, const float* __restrict__ bias, int C, int copyw) {
    int n = blockIdx.x;
    int tid = threadIdx.x;   // 128 threads
    const float* af_in = g_af[sel];
    float* af_out = g_af[sel ^ 1];
    int beg = g_rowptr[n], end = g_rowptr[n + 1];
    float acc[4] = {0.f, 0.f, 0.f, 0.f};
    float oc0 = 0.f, oc1 = 0.f;

    for (int s = beg; s < end; s++) {
        int sn = g_srcS[s];
        const float* hr = g_h + sn * (HH * C);
        const float* ar = g_alpha + s * HH;
        float a[HH];
        #pragma unroll
        for (int h = 0; h < HH; h++) a[h] = ar[h];
        #pragma unroll
        for (int r = 0; r < 4; r++) {
            int c = tid + r * 128;
            if (c < C) {
                float v = 0.f;
                #pragma unroll
                for (int h = 0; h < HH; h++) v = fmaf(a[h], hr[h * C + c], v);
                acc[r] += v;
            }
        }
        if (tid == 0) {
            float sa = 0.f;
            #pragma unroll
            for (int h = 0; h < HH; h++) sa += a[h];
            oc0 = fmaf(sa, af_in[sn * AFS + 0], oc0);
            oc1 = fmaf(sa, af_in[sn * AFS + 1], oc1);
        }
    }
    #pragma unroll
    for (int r = 0; r < 4; r++) {
        int c = tid + r * 128;
        if (c < C)
            af_out[n * AFS + 2 + copyw + c] = seluf(acc[r] * 0.125f + bias[c]);
    }
    if (tid < copyw)
        af_out[n * AFS + 2 + tid] = af_in[n * AFS + tid];
    if (tid == 0) {
        float a0 = af_in[n * AFS + 0], a1 = af_in[n * AFS + 1];
        float c0 = (a0 == 0.f) ? 0.f : ((a0 == 1.f) ? 1.f : oc0 * (0.2f * 0.125f));
        float c1 = (a1 == 1.f) ? 1.f : ((a1 == 0.f) ? 0.f : oc1 * (0.2f * 0.125f));
        af_out[n * AFS + 0] = c0;
        af_out[n * AFS + 1] = c1;
    }
}

// ---------------- final layer: only the coordinate update is needed ----------------
__global__ void k_final(int sel, float* __restrict__ out) {
    int n = blockIdx.x;
    int lane = threadIdx.x;  // 32
    const float* af_in = g_af[sel];
    int beg = g_rowptr[n], end = g_rowptr[n + 1];
    float oc0 = 0.f, oc1 = 0.f;
    for (int s = beg + lane; s < end; s += 32) {
        int sn = g_srcS[s];
        float sa = 0.f;
        #pragma unroll
        for (int h = 0; h < HH; h++) sa += g_alpha[s * HH + h];
        oc0 = fmaf(sa, af_in[sn * AFS + 0], oc0);
        oc1 = fmaf(sa, af_in[sn * AFS + 1], oc1);
    }
    #pragma unroll
    for (int off = 16; off > 0; off >>= 1) {
        oc0 += __shfl_xor_sync(0xFFFFFFFFu, oc0, off);
        oc1 += __shfl_xor_sync(0xFFFFFFFFu, oc1, off);
    }
    if (lane == 0) {
        float a0 = af_in[n * AFS + 0], a1 = af_in[n * AFS + 1];
        float c0 = (a0 == 0.f) ? 0.f : ((a0 == 1.f) ? 1.f : oc0 * (0.2f * 0.125f));
        float c1 = (a1 == 1.f) ? 1.f : ((a1 == 0.f) ? 0.f : oc1 * (0.2f * 0.125f));
        out[n * 2 + 0] = c0;
        out[n * 2 + 1] = c1;
    }
}

// ---------------- launch ----------------
extern "C" void kernel_launch(void* const* d_in, const int* in_sizes, int n_in,
                              void* d_out, int out_size) {
    const float* data = (const float*)d_in[0];
    const int* eidx = (const int*)d_in[1];
    const float* W0 = (const float*)d_in[2];
    const float* b0 = (const float*)d_in[3];
    const float *W[4], *As[4], *Ad[4], *Bi[4];
    for (int i = 0; i < 4; i++) {
        W[i]  = (const float*)d_in[4 + 4 * i];
        As[i] = (const float*)d_in[5 + 4 * i];
        Ad[i] = (const float*)d_in[6 + 4 * i];
        Bi[i] = (const float*)d_in[7 + 4 * i];
    }
    float* out = (float*)d_out;

    k_init<<<(NN + 255) / 256, 256>>>();
    k_count<<<(EP + 255) / 256, 256>>>(eidx);
    k_scan<<<1, 1024>>>();
    k_scatter<<<(EP + 255) / 256, 256>>>(eidx);
    k_layer0<<<NN, 256>>>(data, W0, b0);

    const int Kd[4] = {258, 516, 262, 136};
    const int Cd[4] = {512, 256, 128, 20};
    int sel = 0;
    for (int l = 0; l < 4; l++) {
        int Ncols = HH * Cd[l];
        dim3 gg((Ncols + 127) / 128, (NN + 127) / 128);
        k_gemm<<<gg, 256>>>(sel, W[l], NN, Ncols, Kd[l]);
        k_scores<<<NN, 256>>>(As[l], Ad[l], Cd[l]);
        k_softmax<<<(NN + 7) / 8, 256>>>();
        if (l < 3) {
            k_aggregate<<<NN, 128>>>(sel, Bi[l], Cd[l], 2 * l + 2);
            sel ^= 1;
        } else {
            k_final<<<NN, 32>>>(sel, out);
        }
    }
}

// round 5
// speedup vs baseline: 1.7059x; 1.7059x over previous
#include <cuda_runtime.h>
#include <cuda_bf16.h>
#include <stdint.h>
#include <math.h>

#define NN 5000
#define EE 40000
#define EP 45000      // EE + NN self loops
#define HH 8
#define AFS 520       // padded row stride for node-feature buffers (max width 516)

// ---------------- scratch (static device globals; no allocation) ----------------
__device__ float g_af[2][NN * AFS];      // ping-pong layer inputs [coords, feat..]
__device__ float g_h[NN * 4096];         // GEMM output h = af @ W (max H*C = 4096)
__device__ float g_es[NN * HH];
__device__ float g_ed[NN * HH];
__device__ float g_alpha[EP * HH];
__device__ int   g_cnt[NN];
__device__ int   g_pos[NN];
__device__ int   g_rowptr[NN + 1];
__device__ int   g_srcS[EP];
// split-bf16 operands for tensor-core GEMM
__device__ __nv_bfloat16 g_Ah[NN * 576];
__device__ __nv_bfloat16 g_Al[NN * 576];
__device__ __nv_bfloat16 g_Bh[1310720];   // max N_pad*K_pad = 4096*320
__device__ __nv_bfloat16 g_Bl[1310720];

__device__ __forceinline__ float seluf(float x) {
    const float sc = 1.0507009873554805f, al = 1.6732632423543772f;
    return x > 0.f ? sc * x : sc * al * (expf(x) - 1.f);
}
__device__ __forceinline__ int edge_src(const int* e, int i) { return i < EE ? e[i] : i - EE; }
__device__ __forceinline__ int edge_dst(const int* e, int i) { return i < EE ? e[EE + i] : i - EE; }

__device__ __forceinline__ uint32_t smem_to_u32(const void* p) {
    uint32_t a;
    asm("{ .reg .u64 t; cvta.to.shared.u64 t, %1; cvt.u32.u64 %0, t; }" : "=r"(a) : "l"(p));
    return a;
}
__device__ __forceinline__ void ldmx4(uint32_t* r, uint32_t addr) {
    asm volatile("ldmatrix.sync.aligned.m8n8.x4.shared.b16 {%0,%1,%2,%3}, [%4];"
                 : "=r"(r[0]), "=r"(r[1]), "=r"(r[2]), "=r"(r[3]) : "r"(addr));
}
__device__ __forceinline__ void ldmx2(uint32_t* r, uint32_t addr) {
    asm volatile("ldmatrix.sync.aligned.m8n8.x2.shared.b16 {%0,%1}, [%2];"
                 : "=r"(r[0]), "=r"(r[1]) : "r"(addr));
}
__device__ __forceinline__ void mma16816(float* c, const uint32_t* a, const uint32_t* b) {
    asm volatile("mma.sync.aligned.m16n8k16.row.col.f32.bf16.bf16.f32 "
                 "{%0,%1,%2,%3}, {%4,%5,%6,%7}, {%8,%9}, {%0,%1,%2,%3};"
                 : "+f"(c[0]), "+f"(c[1]), "+f"(c[2]), "+f"(c[3])
                 : "r"(a[0]), "r"(a[1]), "r"(a[2]), "r"(a[3]), "r"(b[0]), "r"(b[1]));
}

// ---------------- CSR build ----------------
__global__ void k_init() {
    int i = blockIdx.x * blockDim.x + threadIdx.x;
    if (i < NN) { g_cnt[i] = 0; g_pos[i] = 0; }
}
__global__ void k_count(const int* __restrict__ eidx) {
    int i = blockIdx.x * blockDim.x + threadIdx.x;
    if (i < EP) atomicAdd(&g_cnt[edge_dst(eidx, i)], 1);
}
__global__ void k_scan() {
    __shared__ int sh[1024];
    const int CH = 5;
    int t = threadIdx.x, base = t * CH;
    int loc[CH]; int s = 0;
    #pragma unroll
    for (int i = 0; i < CH; i++) {
        int idx = base + i;
        int v = (idx < NN) ? g_cnt[idx] : 0;
        loc[i] = s; s += v;
    }
    sh[t] = s;
    __syncthreads();
    for (int off = 1; off < 1024; off <<= 1) {
        int v = (t >= off) ? sh[t - off] : 0;
        __syncthreads();
        sh[t] += v;
        __syncthreads();
    }
    int excl = sh[t] - s;
    #pragma unroll
    for (int i = 0; i < CH; i++) {
        int idx = base + i;
        if (idx < NN) g_rowptr[idx] = excl + loc[i];
    }
    if (t == 1023) g_rowptr[NN] = sh[1023];
}
__global__ void k_scatter(const int* __restrict__ eidx) {
    int i = blockIdx.x * blockDim.x + threadIdx.x;
    if (i >= EP) return;
    int d = edge_dst(eidx, i);
    int p = atomicAdd(&g_pos[d], 1);
    g_srcS[g_rowptr[d] + p] = edge_src(eidx, i);
}

// ---------------- layer 0 ----------------
__global__ void k_layer0(const float* __restrict__ data, const float* __restrict__ W0,
                         const float* __restrict__ b0) {
    int n = blockIdx.x;
    int c = threadIdx.x;
    __shared__ float d[16];
    if (c < 10) d[c] = data[n * 10 + c];
    __syncthreads();
    float s = b0[c];
    #pragma unroll
    for (int k = 0; k < 10; k++) s = fmaf(d[k], W0[k * 256 + c], s);
    g_af[0][n * AFS + 2 + c] = seluf(s);
    if (c < 2) g_af[0][n * AFS + c] = d[c];
}

// ---------------- split-precision conversion ----------------
__global__ void k_convA(int sel, int K, int Kp) {
    int n = blockIdx.x;
    const float* a = g_af[sel] + n * AFS;
    for (int k = threadIdx.x; k < Kp; k += blockDim.x) {
        float v = (k < K) ? a[k] : 0.f;
        __nv_bfloat16 hi = __float2bfloat16(v);
        float lo = v - __bfloat162float(hi);
        g_Ah[n * Kp + k] = hi;
        g_Al[n * Kp + k] = __float2bfloat16(lo);
    }
}
// B: W [K,N] row-major -> g_Bh/g_Bl [N_pad x Kp] (transposed), zero pad
__global__ void k_convB(const float* __restrict__ W, int K, int Ncols, int Kp) {
    __shared__ float sh[32][33];
    int k0 = blockIdx.x * 32, n0 = blockIdx.y * 32;
    int tx = threadIdx.x, ty = threadIdx.y;      // (32, 8)
    #pragma unroll
    for (int i = 0; i < 4; i++) {
        int k = k0 + ty + 8 * i, n = n0 + tx;
        sh[ty + 8 * i][tx] = (k < K && n < Ncols) ? W[k * Ncols + n] : 0.f;
    }
    __syncthreads();
    #pragma unroll
    for (int i = 0; i < 4; i++) {
        int n = n0 + ty + 8 * i, k = k0 + tx;
        float v = sh[tx][ty + 8 * i];
        __nv_bfloat16 hi = __float2bfloat16(v);
        float lo = v - __bfloat162float(hi);
        g_Bh[n * Kp + k] = hi;
        g_Bl[n * Kp + k] = __float2bfloat16(lo);
    }
}

// ---------------- mma.sync bf16x3 GEMM: g_h[M,Nc] = A @ B^T ----------------
// 128x128 CTA tile, BK=32, 8 warps (2x4), warp tile 64x32, static smem (~40KB).
#define BM 128
#define BN 128
#define BK 32
#define ASTR 40   // BK + 8 pad; 80B row stride -> conflict-free ldmatrix

__global__ void __launch_bounds__(256, 2) k_mma_sync(int Kp, int M, int Nc) {
    __shared__ __align__(16) __nv_bfloat16 sAh[BM][ASTR];
    __shared__ __align__(16) __nv_bfloat16 sAl[BM][ASTR];
    __shared__ __align__(16) __nv_bfloat16 sBh[BN][ASTR];
    __shared__ __align__(16) __nv_bfloat16 sBl[BN][ASTR];

    const int tid = threadIdx.x, lane = tid & 31, wid = tid >> 5;
    const int warp_m = wid >> 2, warp_n = wid & 3;
    const int bm = blockIdx.y * BM, bn = blockIdx.x * BN;

    const uint32_t bAh = smem_to_u32(&sAh[0][0]);
    const uint32_t bAl = smem_to_u32(&sAl[0][0]);
    const uint32_t bBh = smem_to_u32(&sBh[0][0]);
    const uint32_t bBl = smem_to_u32(&sBl[0][0]);

    // per-lane ldmatrix row/col components
    const int a_row = lane & 15, a_hi = lane >> 4;        // x4: rows 0-15, k / k+8
    const int b_row = lane & 7,  b_hi = (lane >> 3) & 1;  // x2: rows 0-7,  k / k+8

    float acc[4][4][4];
    #pragma unroll
    for (int i = 0; i < 4; i++)
        #pragma unroll
        for (int j = 0; j < 4; j++)
            #pragma unroll
            for (int t = 0; t < 4; t++) acc[i][j][t] = 0.f;

    for (int k0 = 0; k0 < Kp; k0 += BK) {
        __syncthreads();
        #pragma unroll
        for (int it = 0; it < 2; it++) {
            int c = tid + it * 256;            // 512 chunks of 16B per operand
            int row = c >> 2, c8 = c & 3;
            int gr = bm + row;
            uint4 vh = make_uint4(0, 0, 0, 0), vl = make_uint4(0, 0, 0, 0);
            if (gr < M) {
                vh = *(const uint4*)&g_Ah[(size_t)gr * Kp + k0 + c8 * 8];
                vl = *(const uint4*)&g_Al[(size_t)gr * Kp + k0 + c8 * 8];
            }
            *(uint4*)&sAh[row][c8 * 8] = vh;
            *(uint4*)&sAl[row][c8 * 8] = vl;
            int gn = bn + row;
            *(uint4*)&sBh[row][c8 * 8] = *(const uint4*)&g_Bh[(size_t)gn * Kp + k0 + c8 * 8];
            *(uint4*)&sBl[row][c8 * 8] = *(const uint4*)&g_Bl[(size_t)gn * Kp + k0 + c8 * 8];
        }
        __syncthreads();

        #pragma unroll
        for (int ks = 0; ks < 2; ks++) {
            uint32_t bh[4][2], bl[4][2];
            #pragma unroll
            for (int j = 0; j < 4; j++) {
                uint32_t off = (uint32_t)(((warp_n * 32 + j * 8 + b_row) * ASTR
                                           + ks * 16 + b_hi * 8) * 2);
                ldmx2(bh[j], bBh + off);
                ldmx2(bl[j], bBl + off);
            }
            #pragma unroll
            for (int i = 0; i < 4; i++) {
                uint32_t ah[4], al[4];
                uint32_t off = (uint32_t)(((warp_m * 64 + i * 16 + a_row) * ASTR
                                           + ks * 16 + a_hi * 8) * 2);
                ldmx4(ah, bAh + off);
                ldmx4(al, bAl + off);
                #pragma unroll
                for (int j = 0; j < 4; j++) {
                    mma16816(acc[i][j], ah, bh[j]);
                    mma16816(acc[i][j], ah, bl[j]);
                    mma16816(acc[i][j], al, bh[j]);
                }
            }
        }
    }

    // epilogue: accumulator layout c0,c1 -> (m, n..n+1); c2,c3 -> (m+8, n..n+1)
    #pragma unroll
    for (int i = 0; i < 4; i++) {
        int m0 = bm + warp_m * 64 + i * 16 + (lane >> 2);
        #pragma unroll
        for (int j = 0; j < 4; j++) {
            int n0 = bn + warp_n * 32 + j * 8 + (lane & 3) * 2;
            if (n0 < Nc) {
                if (m0 < M)
                    *(float2*)&g_h[(size_t)m0 * Nc + n0] = make_float2(acc[i][j][0], acc[i][j][1]);
                if (m0 + 8 < M)
                    *(float2*)&g_h[(size_t)(m0 + 8) * Nc + n0] = make_float2(acc[i][j][2], acc[i][j][3]);
            }
        }
    }
}

// ---------------- per-node attention scores ----------------
__global__ void k_scores(const float* __restrict__ asrc, const float* __restrict__ adst, int C) {
    int n = blockIdx.x;
    int wid = threadIdx.x >> 5, lane = threadIdx.x & 31;
    const float* hr = g_h + (size_t)n * (HH * C) + wid * C;
    const float* as = asrc + wid * C;
    const float* ad = adst + wid * C;
    float s1 = 0.f, s2 = 0.f;
    for (int c = lane; c < C; c += 32) {
        float v = hr[c];
        s1 = fmaf(v, as[c], s1);
        s2 = fmaf(v, ad[c], s2);
    }
    #pragma unroll
    for (int off = 16; off > 0; off >>= 1) {
        s1 += __shfl_xor_sync(0xFFFFFFFFu, s1, off);
        s2 += __shfl_xor_sync(0xFFFFFFFFu, s2, off);
    }
    if (!lane) { g_es[n * HH + wid] = s1; g_ed[n * HH + wid] = s2; }
}

// ---------------- edge softmax ----------------
__global__ void k_softmax() {
    int warp = (blockIdx.x * blockDim.x + threadIdx.x) >> 5;
    if (warp >= NN) return;
    int lane = threadIdx.x & 31;
    int n = warp;
    int beg = g_rowptr[n], end = g_rowptr[n + 1];
    int el = lane >> 3;
    int hh = lane & 7;
    float edv = g_ed[n * HH + hh];

    float mx = -INFINITY;
    for (int s = beg; s < end; s += 4) {
        int si = s + el;
        float lg = -INFINITY;
        if (si < end) {
            float x = g_es[g_srcS[si] * HH + hh] + edv;
            lg = x >= 0.f ? x : 0.2f * x;
        }
        mx = fmaxf(mx, lg);
    }
    mx = fmaxf(mx, __shfl_xor_sync(0xFFFFFFFFu, mx, 8));
    mx = fmaxf(mx, __shfl_xor_sync(0xFFFFFFFFu, mx, 16));

    float se = 0.f;
    for (int s = beg; s < end; s += 4) {
        int si = s + el;
        if (si < end) {
            float x = g_es[g_srcS[si] * HH + hh] + edv;
            x = x >= 0.f ? x : 0.2f * x;
            se += expf(x - mx);
        }
    }
    se += __shfl_xor_sync(0xFFFFFFFFu, se, 8);
    se += __shfl_xor_sync(0xFFFFFFFFu, se, 16);
    float inv = 1.f / se;

    for (int s = beg; s < end; s += 4) {
        int si = s + el;
        if (si < end) {
            float x = g_es[g_srcS[si] * HH + hh] + edv;
            x = x >= 0.f ? x : 0.2f * x;
            g_alpha[si * HH + hh] = expf(x - mx) * inv;
        }
    }
}

// ---------------- aggregation + coord update + next-layer assembly ----------------
__global__ void k_aggregate(int sel, const float* __restrict__ bias, int C, int copyw) {
    int n = blockIdx.x;
    int tid = threadIdx.x;   // 128
    const float* af_in = g_af[sel];
    float* af_out = g_af[sel ^ 1];
    int beg = g_rowptr[n], end = g_rowptr[n + 1];
    float acc[4] = {0.f, 0.f, 0.f, 0.f};
    float oc0 = 0.f, oc1 = 0.f;

    for (int s = beg; s < end; s++) {
        int sn = g_srcS[s];
        const float* hr = g_h + (size_t)sn * (HH * C);
        const float* ar = g_alpha + s * HH;
        float a[HH];
        #pragma unroll
        for (int h = 0; h < HH; h++) a[h] = ar[h];
        #pragma unroll
        for (int r = 0; r < 4; r++) {
            int c = tid + r * 128;
            if (c < C) {
                float v = 0.f;
                #pragma unroll
                for (int h = 0; h < HH; h++) v = fmaf(a[h], hr[h * C + c], v);
                acc[r] += v;
            }
        }
        if (tid == 0) {
            float sa = 0.f;
            #pragma unroll
            for (int h = 0; h < HH; h++) sa += a[h];
            oc0 = fmaf(sa, af_in[sn * AFS + 0], oc0);
            oc1 = fmaf(sa, af_in[sn * AFS + 1], oc1);
        }
    }
    #pragma unroll
    for (int r = 0; r < 4; r++) {
        int c = tid + r * 128;
        if (c < C)
            af_out[n * AFS + 2 + copyw + c] = seluf(acc[r] * 0.125f + bias[c]);
    }
    if (tid < copyw)
        af_out[n * AFS + 2 + tid] = af_in[n * AFS + tid];
    if (tid == 0) {
        float a0 = af_in[n * AFS + 0], a1 = af_in[n * AFS + 1];
        float c0 = (a0 == 0.f) ? 0.f : ((a0 == 1.f) ? 1.f : oc0 * (0.2f * 0.125f));
        float c1 = (a1 == 1.f) ? 1.f : ((a1 == 0.f) ? 0.f : oc1 * (0.2f * 0.125f));
        af_out[n * AFS + 0] = c0;
        af_out[n * AFS + 1] = c1;
    }
}

// ---------------- final layer ----------------
__global__ void k_final(int sel, float* __restrict__ out) {
    int n = blockIdx.x;
    int lane = threadIdx.x;
    const float* af_in = g_af[sel];
    int beg = g_rowptr[n], end = g_rowptr[n + 1];
    float oc0 = 0.f, oc1 = 0.f;
    for (int s = beg + lane; s < end; s += 32) {
        int sn = g_srcS[s];
        float sa = 0.f;
        #pragma unroll
        for (int h = 0; h < HH; h++) sa += g_alpha[s * HH + h];
        oc0 = fmaf(sa, af_in[sn * AFS + 0], oc0);
        oc1 = fmaf(sa, af_in[sn * AFS + 1], oc1);
    }
    #pragma unroll
    for (int off = 16; off > 0; off >>= 1) {
        oc0 += __shfl_xor_sync(0xFFFFFFFFu, oc0, off);
        oc1 += __shfl_xor_sync(0xFFFFFFFFu, oc1, off);
    }
    if (lane == 0) {
        float a0 = af_in[n * AFS + 0], a1 = af_in[n * AFS + 1];
        float c0 = (a0 == 0.f) ? 0.f : ((a0 == 1.f) ? 1.f : oc0 * (0.2f * 0.125f));
        float c1 = (a1 == 1.f) ? 1.f : ((a1 == 0.f) ? 0.f : oc1 * (0.2f * 0.125f));
        out[n * 2 + 0] = c0;
        out[n * 2 + 1] = c1;
    }
}

// ---------------- launch ----------------
extern "C" void kernel_launch(void* const* d_in, const int* in_sizes, int n_in,
                              void* d_out, int out_size) {
    const float* data = (const float*)d_in[0];
    const int* eidx = (const int*)d_in[1];
    const float* W0 = (const float*)d_in[2];
    const float* b0 = (const float*)d_in[3];
    const float *W[4], *As[4], *Ad[4], *Bi[4];
    for (int i = 0; i < 4; i++) {
        W[i]  = (const float*)d_in[4 + 4 * i];
        As[i] = (const float*)d_in[5 + 4 * i];
        Ad[i] = (const float*)d_in[6 + 4 * i];
        Bi[i] = (const float*)d_in[7 + 4 * i];
    }
    float* out = (float*)d_out;

    k_init<<<(NN + 255) / 256, 256>>>();
    k_count<<<(EP + 255) / 256, 256>>>(eidx);
    k_scan<<<1, 1024>>>();
    k_scatter<<<(EP + 255) / 256, 256>>>(eidx);
    k_layer0<<<NN, 256>>>(data, W0, b0);

    const int Kd[4]  = {258, 516, 262, 136};
    const int Kpd[4] = {320, 576, 320, 192};
    const int Cd[4]  = {512, 256, 128, 20};
    int sel = 0;
    for (int l = 0; l < 4; l++) {
        int Nc = HH * Cd[l];                       // 4096, 2048, 1024, 160
        int Npad = (Nc + 127) & ~127;              // 4096, 2048, 1024, 256
        int K = Kd[l], Kp = Kpd[l];
        k_convA<<<NN, 256>>>(sel, K, Kp);
        dim3 gb(Kp / 32, Npad / 32);
        k_convB<<<gb, dim3(32, 8)>>>(W[l], K, Nc, Kp);
        dim3 gg(Npad / 128, (NN + 127) / 128);
        k_mma_sync<<<gg, 256>>>(Kp, NN, Nc);
        k_scores<<<NN, 256>>>(As[l], Ad[l], Cd[l]);
        k_softmax<<<(NN + 7) / 8, 256>>>();
        if (l < 3) {
            k_aggregate<<<NN, 128>>>(sel, Bi[l], Cd[l], 2 * l + 2);
            sel ^= 1;
        } else {
            k_final<<<NN, 32>>>(sel, out);
        }
    }
}